// round 1
// baseline (speedup 1.0000x reference)
#include <cuda_runtime.h>
#include <math_constants.h>

// Problem shapes (PointCloudMeshGridLoss_79070347920145)
#define NB 2
#define NP 8192
#define NV 4098
#define NF 8192
#define EPSF 1e-12f

// Main kernel tiling
#define THREADS   256
#define NPT       2                       // points per thread
#define PTS_BLOCK (THREADS * NPT)         // 512 points per block
#define PTILES    (NP / PTS_BLOCK)        // 16
#define SLICES    8
#define TRI_SLICE (NF / SLICES)           // 1024 triangles per slice
#define TRI_TILE  512                     // triangles staged in smem at once (32KB)

// Scratch (no cudaMalloc allowed): precomputed triangle data + per-point min d^2
// Triangle record (4 x float4 = 64B):
//  q0: ax ay az abx | q1: aby abz acx acy | q2: acz aa ad cc | q3: raa rcc rbb rden
__device__ float4 g_tri[NB * NF * 4];
__device__ float  g_mind2[NB * NP];

// ---------------------------------------------------------------------------
// Kernel 1: per-triangle precompute
// ---------------------------------------------------------------------------
__global__ void prep_kernel(const float* __restrict__ verts,
                            const int*   __restrict__ faces) {
    int idx = blockIdx.x * blockDim.x + threadIdx.x;
    if (idx >= NB * NF) return;
    int b = idx / NF;
    int f = idx - b * NF;

    const int* fc = faces + ((size_t)b * NF + f) * 3;
    const float* vb = verts + (size_t)b * NV * 3;
    int ia = fc[0], ibv = fc[1], ic = fc[2];

    float ax = vb[ia * 3 + 0], ay = vb[ia * 3 + 1], az = vb[ia * 3 + 2];
    float bx = vb[ibv * 3 + 0], by = vb[ibv * 3 + 1], bz = vb[ibv * 3 + 2];
    float cx = vb[ic * 3 + 0], cy = vb[ic * 3 + 1], cz = vb[ic * 3 + 2];

    float abx = bx - ax, aby = by - ay, abz = bz - az;
    float acx = cx - ax, acy = cy - ay, acz = cz - az;

    float aa = abx * abx + aby * aby + abz * abz;   // |ab|^2 = d1 - d3
    float ad = abx * acx + aby * acy + abz * acz;   // ab.ac
    float cc = acx * acx + acy * acy + acz * acz;   // |ac|^2 = d2 - d6
    float bb = aa + cc - 2.0f * ad;                 // |bc|^2 = (d4-d3)+(d5-d6)
    float den = aa * cc - ad * ad;                  // va + vb + vc

    float raa  = 1.0f / fmaxf(aa, EPSF);
    float rcc  = 1.0f / fmaxf(cc, EPSF);
    float rbb  = 1.0f / fmaxf(bb, EPSF);
    float rden = 1.0f / fmaxf(den, EPSF);

    float4* o = &g_tri[(size_t)idx * 4];
    o[0] = make_float4(ax, ay, az, abx);
    o[1] = make_float4(aby, abz, acx, acy);
    o[2] = make_float4(acz, aa, ad, cc);
    o[3] = make_float4(raa, rcc, rbb, rden);
}

// ---------------------------------------------------------------------------
// Kernel 2: init per-point min to +inf
// ---------------------------------------------------------------------------
__global__ void init_mind2() {
    int i = blockIdx.x * blockDim.x + threadIdx.x;
    if (i < NB * NP) g_mind2[i] = CUDART_INF_F;
}

// ---------------------------------------------------------------------------
// Kernel 3: main point-triangle distance scan.
// Exact replication of the reference region cascade (Ericson 5.1.5),
// with all reciprocals precomputed per-triangle (no division in the loop).
// ---------------------------------------------------------------------------
__global__ __launch_bounds__(THREADS)
void main_kernel(const float* __restrict__ points) {
    __shared__ float4 s_tri[TRI_TILE * 4];   // 32 KB

    const int b     = blockIdx.z;
    const int ptile = blockIdx.x;
    const int slice = blockIdx.y;

    // Load this thread's points
    float px[NPT], py[NPT], pz[NPT], best[NPT];
#pragma unroll
    for (int k = 0; k < NPT; ++k) {
        int p = ptile * PTS_BLOCK + k * THREADS + threadIdx.x;
        const float* pp = points + ((size_t)b * NP + p) * 3;
        px[k] = pp[0]; py[k] = pp[1]; pz[k] = pp[2];
        best[k] = CUDART_INF_F;
    }

    const int tri0 = slice * TRI_SLICE;
    for (int tile = 0; tile < TRI_SLICE; tile += TRI_TILE) {
        __syncthreads();
        const float4* src = &g_tri[((size_t)b * NF + tri0 + tile) * 4];
        for (int i = threadIdx.x; i < TRI_TILE * 4; i += THREADS)
            s_tri[i] = src[i];
        __syncthreads();

#pragma unroll 2
        for (int t = 0; t < TRI_TILE; ++t) {
            float4 q0 = s_tri[t * 4 + 0];
            float4 q1 = s_tri[t * 4 + 1];
            float4 q2 = s_tri[t * 4 + 2];
            float4 q3 = s_tri[t * 4 + 3];
            float ax = q0.x, ay = q0.y, az = q0.z;
            float abx = q0.w, aby = q1.x, abz = q1.y;
            float acx = q1.z, acy = q1.w, acz = q2.x;
            float aa = q2.y, ad = q2.z, cc = q2.w;
            float raa = q3.x, rcc = q3.y, rbb = q3.z, rden = q3.w;

#pragma unroll
            for (int k = 0; k < NPT; ++k) {
                float apx = px[k] - ax;
                float apy = py[k] - ay;
                float apz = pz[k] - az;

                float d1 = fmaf(abx, apx, fmaf(aby, apy, abz * apz));
                float d2 = fmaf(acx, apx, fmaf(acy, apy, acz * apz));
                float d3 = d1 - aa;
                float d4 = d2 - ad;
                float d5 = d1 - ad;
                float d6 = d2 - cc;

                float va = d3 * d6 - d5 * d4;
                float vbv = d5 * d2 - d1 * d6;
                float vcv = d1 * d4 - d3 * d2;

                // interior (lowest priority)
                float s = vbv * rden;
                float w = vcv * rden;

                // cond6: edge BC
                float e46 = d4 - d3;
                float e56 = d5 - d6;
                bool c6 = (va <= 0.0f) && (e46 >= 0.0f) && (e56 >= 0.0f);
                float wbc = e46 * rbb;
                s = c6 ? (1.0f - wbc) : s;
                w = c6 ? wbc : w;

                // cond5: edge AC
                bool c5 = (vbv <= 0.0f) && (d2 >= 0.0f) && (d6 <= 0.0f);
                s = c5 ? 0.0f : s;
                w = c5 ? (d2 * rcc) : w;

                // cond4: edge AB
                bool c4 = (vcv <= 0.0f) && (d1 >= 0.0f) && (d3 <= 0.0f);
                s = c4 ? (d1 * raa) : s;
                w = c4 ? 0.0f : w;

                // cond3: vertex C
                bool c3 = (d6 >= 0.0f) && (d5 <= d6);
                s = c3 ? 0.0f : s;
                w = c3 ? 1.0f : w;

                // cond2: vertex B
                bool c2 = (d3 >= 0.0f) && (d4 <= d3);
                s = c2 ? 1.0f : s;
                w = c2 ? 0.0f : w;

                // cond1: vertex A (highest priority)
                bool c1 = (d1 <= 0.0f) && (d2 <= 0.0f);
                s = c1 ? 0.0f : s;
                w = c1 ? 0.0f : w;

                // residual = ap - s*ab - w*ac ; d^2 = |residual|^2
                float rx = apx - fmaf(s, abx, w * acx);
                float ry = apy - fmaf(s, aby, w * acy);
                float rz = apz - fmaf(s, abz, w * acz);
                float dd = fmaf(rx, rx, fmaf(ry, ry, rz * rz));

                best[k] = fminf(best[k], dd);
            }
        }
    }

    // Combine across triangle slices. d^2 >= 0 so int-compare == float-compare.
#pragma unroll
    for (int k = 0; k < NPT; ++k) {
        int p = ptile * PTS_BLOCK + k * THREADS + threadIdx.x;
        atomicMin((int*)&g_mind2[b * NP + p], __float_as_int(best[k]));
    }
}

// ---------------------------------------------------------------------------
// Kernel 4: finalize — sum per-point mins, height, sqrt, mean over batch.
// Single block, 1024 threads, deterministic tree reductions.
// ---------------------------------------------------------------------------
__device__ __forceinline__ float warpSum(float v) {
#pragma unroll
    for (int o = 16; o > 0; o >>= 1) v += __shfl_down_sync(0xffffffffu, v, o);
    return v;
}
__device__ __forceinline__ float warpMax(float v) {
#pragma unroll
    for (int o = 16; o > 0; o >>= 1) v = fmaxf(v, __shfl_down_sync(0xffffffffu, v, o));
    return v;
}
__device__ __forceinline__ float warpMin(float v) {
#pragma unroll
    for (int o = 16; o > 0; o >>= 1) v = fminf(v, __shfl_down_sync(0xffffffffu, v, o));
    return v;
}

__global__ void finalize_kernel(const float* __restrict__ verts,
                                float* __restrict__ out) {
    __shared__ float sred[32];
    __shared__ float sres[4];  // [0..1] = losses, scratch broadcast
    int tid = threadIdx.x;
    int lane = tid & 31, wrp = tid >> 5;
    int nwarps = blockDim.x >> 5;

    for (int b = 0; b < NB; ++b) {
        // sum of min d^2
        float sum = 0.0f;
        for (int i = tid; i < NP; i += blockDim.x) sum += g_mind2[b * NP + i];
        sum = warpSum(sum);
        __syncthreads();
        if (lane == 0) sred[wrp] = sum;
        __syncthreads();
        if (wrp == 0) {
            float v = (lane < nwarps) ? sred[lane] : 0.0f;
            v = warpSum(v);
            if (lane == 0) sres[2] = v;
        }
        __syncthreads();
        float total = sres[2];

        // height = max(y) - min(y)
        float ymax = -CUDART_INF_F, ymin = CUDART_INF_F;
        for (int i = tid; i < NV; i += blockDim.x) {
            float y = verts[((size_t)b * NV + i) * 3 + 1];
            ymax = fmaxf(ymax, y);
            ymin = fminf(ymin, y);
        }
        ymax = warpMax(ymax);
        __syncthreads();
        if (lane == 0) sred[wrp] = ymax;
        __syncthreads();
        if (wrp == 0) {
            float v = (lane < nwarps) ? sred[lane] : -CUDART_INF_F;
            v = warpMax(v);
            if (lane == 0) sres[3] = v;
        }
        __syncthreads();
        float hmax = sres[3];

        ymin = warpMin(ymin);
        __syncthreads();
        if (lane == 0) sred[wrp] = ymin;
        __syncthreads();
        if (wrp == 0) {
            float v = (lane < nwarps) ? sred[lane] : CUDART_INF_F;
            v = warpMin(v);
            if (lane == 0) sres[3] = v;
        }
        __syncthreads();
        float hmin = sres[3];

        if (tid == 0) sres[b] = sqrtf(total) / (hmax - hmin);
        __syncthreads();
    }

    if (tid == 0) out[0] = 0.5f * (sres[0] + sres[1]);  // mean * LOSS_WEIGHT(=1)
}

// ---------------------------------------------------------------------------
// Entry point
// ---------------------------------------------------------------------------
extern "C" void kernel_launch(void* const* d_in, const int* in_sizes, int n_in,
                              void* d_out, int out_size) {
    const float* points = (const float*)d_in[0];  // body_verts [2,8192,3]
    const float* verts  = (const float*)d_in[1];  // mesh_verts [2,4098,3]
    const int*   faces  = (const int*)d_in[2];    // faces      [2,8192,3]
    float* out = (float*)d_out;

    init_mind2<<<(NB * NP + 255) / 256, 256>>>();
    prep_kernel<<<(NB * NF + 255) / 256, 256>>>(verts, faces);

    dim3 grid(PTILES, SLICES, NB);
    main_kernel<<<grid, THREADS>>>(points);

    finalize_kernel<<<1, 1024>>>(verts, out);
}

// round 3
// speedup vs baseline: 1.4254x; 1.4254x over previous
#include <cuda_runtime.h>
#include <math_constants.h>

// Problem shapes (PointCloudMeshGridLoss_79070347920145)
#define NB 2
#define NP 8192
#define NV 4098
#define NF 8192
#define EPSF 1e-12f

#define THREADS   256
#define PTS_BLOCK 512                 // 2 points per thread, packed f32x2
#define PTILES    16                  // NP / PTS_BLOCK
#define TRI_CHUNK 128
#define NCHUNKS   64                  // NF / TRI_CHUNK
#define UNITS     2048                // NB * PTILES * NCHUNKS
#define GRID      296                 // 148 SMs * 2 resident blocks
#define DEG_MAX   512

typedef unsigned long long u64;

// Per-triangle record: 21 pre-duplicated f32x2 constants + pad = 11 ulonglong2 (176B)
// slot: 0 nax 1 nay 2 naz 3 abx 4 aby 5 abz 6 acx 7 acy 8 acz 9 aa 10 cc
//       11 nad 12 amd 13 bb 14 raa 15 rcc 16 rbb 17 nx 18 ny 19 nz 20 denq 21 pad
__device__ ulonglong2 g_tri[NB * NF * 11];
__device__ float      g_mind2[NB * NP];
__device__ int        g_degcnt[NB];
__device__ int        g_deglist[NB][DEG_MAX];

// ---------------- packed f32x2 helpers ----------------
__device__ __forceinline__ u64 pk2(float lo, float hi) {
    return ((u64)__float_as_uint(hi) << 32) | (u64)__float_as_uint(lo);
}
__device__ __forceinline__ float lo2(u64 v) { return __uint_as_float((unsigned)v); }
__device__ __forceinline__ float hi2(u64 v) { return __uint_as_float((unsigned)(v >> 32)); }
__device__ __forceinline__ u64 f2fma(u64 a, u64 b, u64 c) {
    u64 d; asm("fma.rn.f32x2 %0, %1, %2, %3;" : "=l"(d) : "l"(a), "l"(b), "l"(c)); return d;
}
__device__ __forceinline__ u64 f2mul(u64 a, u64 b) {
    u64 d; asm("mul.rn.f32x2 %0, %1, %2;" : "=l"(d) : "l"(a), "l"(b)); return d;
}
__device__ __forceinline__ u64 f2add(u64 a, u64 b) {
    u64 d; asm("add.rn.f32x2 %0, %1, %2;" : "=l"(d) : "l"(a), "l"(b)); return d;
}
__device__ __forceinline__ u64 f2sat(u64 v) {   // clamp both halves to [0,1]
    float a = fminf(fmaxf(lo2(v), 0.0f), 1.0f);
    float b = fminf(fmaxf(hi2(v), 0.0f), 1.0f);
    return pk2(a, b);
}

// ---------------------------------------------------------------------------
// Kernel 1: per-triangle precompute. Degenerate/near-degenerate faces (the
// only cases where reference's EPS-clamped cascade != true distance) are
// excluded from the fast path (vertex shifted to 1e18 -> candidates ~1e36)
// and appended to a per-batch list handled exactly by correction_kernel.
// ---------------------------------------------------------------------------
__global__ void prep_kernel(const float* __restrict__ verts,
                            const int*   __restrict__ faces) {
    int idx = blockIdx.x * blockDim.x + threadIdx.x;
    if (idx >= NB * NF) return;
    int b = idx / NF;
    int f = idx - b * NF;

    const int* fc = faces + ((size_t)b * NF + f) * 3;
    const float* vb = verts + (size_t)b * NV * 3;
    int ia = fc[0], ib = fc[1], ic = fc[2];

    float ax = vb[ia * 3 + 0], ay = vb[ia * 3 + 1], az = vb[ia * 3 + 2];
    float bx = vb[ib * 3 + 0], by = vb[ib * 3 + 1], bz = vb[ib * 3 + 2];
    float cx = vb[ic * 3 + 0], cy = vb[ic * 3 + 1], cz = vb[ic * 3 + 2];

    float abx = bx - ax, aby = by - ay, abz = bz - az;
    float acx = cx - ax, acy = cy - ay, acz = cz - az;

    float aa = abx * abx + aby * aby + abz * abz;
    float ad = abx * acx + aby * acy + abz * acz;
    float cc = acx * acx + acy * acy + acz * acz;
    float bb = aa + cc - 2.0f * ad;                 // |bc|^2
    float den = aa * cc - ad * ad;                  // |ab x ac|^2

    bool deg = (aa < 1e-9f) || (cc < 1e-9f) || (bb < 1e-9f) || (den < 1e-6f);
    if (deg) {
        int w = atomicAdd(&g_degcnt[b], 1);
        if (w < DEG_MAX) g_deglist[b][w] = f;
    }

    float raa = 1.0f / fmaxf(aa, EPSF);
    float rcc = 1.0f / fmaxf(cc, EPSF);
    float rbb = 1.0f / fmaxf(bb, EPSF);

    // unit normal
    float nxv = aby * acz - abz * acy;
    float nyv = abz * acx - abx * acz;
    float nzv = abx * acy - aby * acx;
    float rn = rsqrtf(fmaxf(den, 1e-30f));
    nxv *= rn; nyv *= rn; nzv *= rn;

    float shift = deg ? 1e18f : 0.0f;
    float denq = (deg || den <= EPSF) ? -1.0f : den;

    u64 s[22];
#define DUP(x) pk2((x), (x))
    s[0]  = DUP(-(ax + shift));  s[1]  = DUP(-(ay + shift));  s[2]  = DUP(-(az + shift));
    s[3]  = DUP(abx);  s[4]  = DUP(aby);  s[5]  = DUP(abz);
    s[6]  = DUP(acx);  s[7]  = DUP(acy);  s[8]  = DUP(acz);
    s[9]  = DUP(aa);   s[10] = DUP(cc);   s[11] = DUP(-ad);
    s[12] = DUP(aa - ad); s[13] = DUP(bb);
    s[14] = DUP(raa);  s[15] = DUP(rcc);  s[16] = DUP(rbb);
    s[17] = DUP(nxv);  s[18] = DUP(nyv);  s[19] = DUP(nzv);
    s[20] = DUP(denq); s[21] = 0ull;
#undef DUP
    ulonglong2* o = &g_tri[(size_t)idx * 11];
#pragma unroll
    for (int j = 0; j < 11; ++j) o[j] = make_ulonglong2(s[2 * j], s[2 * j + 1]);
}

// ---------------------------------------------------------------------------
// Kernel 2: init per-point min to +inf, reset degenerate counters
// ---------------------------------------------------------------------------
__global__ void init_mind2() {
    int i = blockIdx.x * blockDim.x + threadIdx.x;
    if (i < NB * NP) g_mind2[i] = CUDART_INF_F;
    if (i < NB) g_degcnt[i] = 0;
}

// ---------------------------------------------------------------------------
// Kernel 3: main scan — packed f32x2 min-of-candidates (exact true distance,
// identical to reference cascade for all non-degenerate faces)
// ---------------------------------------------------------------------------
__global__ __launch_bounds__(THREADS, 2)
void main_kernel(const float* __restrict__ points) {
    __shared__ ulonglong2 s_tri[TRI_CHUNK * 11];   // 22.5 KB

    const u64 NEG2    = 0xC0000000C0000000ULL;     // (-2, -2)
    const u64 NEGONE2 = 0xBF800000BF800000ULL;     // (-1, -1)

    for (int u = blockIdx.x; u < UNITS; u += GRID) {
        int b     = u >> 10;
        int rem   = u & 1023;
        int ptile = rem >> 6;
        int chunk = rem & 63;

        __syncthreads();
        {
            const ulonglong2* src = &g_tri[((size_t)b * NF + (size_t)chunk * TRI_CHUNK) * 11];
            for (int i = threadIdx.x; i < TRI_CHUNK * 11; i += THREADS)
                s_tri[i] = src[i];
        }

        int p0 = ptile * PTS_BLOCK + threadIdx.x;
        const float* P = points + ((size_t)b * NP + p0) * 3;
        u64 px = pk2(P[0], P[THREADS * 3 + 0]);
        u64 py = pk2(P[1], P[THREADS * 3 + 1]);
        u64 pz = pk2(P[2], P[THREADS * 3 + 2]);
        float best0 = CUDART_INF_F, best1 = CUDART_INF_F;

        __syncthreads();

        for (int t = 0; t < TRI_CHUNK; ++t) {
            const ulonglong2* ct = &s_tri[t * 11];
            ulonglong2 q0 = ct[0], q1 = ct[1], q2 = ct[2], q3 = ct[3], q4 = ct[4];
            ulonglong2 q5 = ct[5], q6 = ct[6], q7 = ct[7], q8 = ct[8], q9 = ct[9];
            u64 den2 = ct[10].x;
            u64 nax = q0.x, nay = q0.y, naz = q1.x, abx = q1.y, aby = q2.x, abz = q2.y;
            u64 acx = q3.x, acy = q3.y, acz = q4.x, aa = q4.y, cc = q5.x, nad = q5.y;
            u64 amd = q6.x, bb = q6.y, raa = q7.x, rcc = q7.y, rbb = q8.x;
            u64 nx = q8.y, ny = q9.x, nz = q9.y;

            u64 apx = f2add(px, nax);
            u64 apy = f2add(py, nay);
            u64 apz = f2add(pz, naz);

            u64 d1 = f2fma(abz, apz, f2fma(aby, apy, f2mul(abx, apx)));
            u64 d2 = f2fma(acz, apz, f2fma(acy, apy, f2mul(acx, apx)));
            u64 pp = f2fma(apz, apz, f2fma(apy, apy, f2mul(apx, apx)));

            // edge AB: d^2 = pp + aa*t*(t - 2*t_hat), t = sat(t_hat), t_hat = d1/aa
            u64 thA = f2mul(d1, raa);
            u64 tA  = f2sat(thA);
            u64 sA  = f2fma(thA, NEG2, tA);
            u64 wA  = f2mul(aa, tA);
            u64 cAB = f2fma(wA, sA, pp);

            // edge AC
            u64 thC = f2mul(d2, rcc);
            u64 tC  = f2sat(thC);
            u64 sC  = f2fma(thC, NEG2, tC);
            u64 wC  = f2mul(cc, tC);
            u64 cAC = f2fma(wC, sC, pp);

            // edge BC
            u64 e46 = f2fma(d1, NEGONE2, f2add(d2, amd));
            u64 thB = f2mul(e46, rbb);
            u64 tB  = f2sat(thB);
            u64 sB  = f2fma(thB, NEG2, tB);
            u64 wB  = f2mul(bb, tB);
            u64 bpp = f2add(f2fma(d1, NEG2, pp), aa);
            u64 cBC = f2fma(wB, sB, bpp);

            // inside test
            u64 vbp = f2fma(nad, d2, f2mul(cc, d1));
            u64 vcp = f2fma(nad, d1, f2mul(aa, d2));
            u64 vs  = f2add(vbp, vcp);

            // plane distance^2
            u64 dp  = f2fma(nz, apz, f2fma(ny, apy, f2mul(nx, apx)));
            u64 dsq = f2mul(dp, dp);

            float den = lo2(den2);
            {
                bool in0 = (lo2(vbp) >= 0.0f) && (lo2(vcp) >= 0.0f) && (lo2(vs) <= den);
                float cpl = in0 ? lo2(dsq) : CUDART_INF_F;
                float m = fminf(fminf(lo2(cAB), lo2(cAC)), fminf(lo2(cBC), cpl));
                best0 = fminf(best0, m);
            }
            {
                bool in1 = (hi2(vbp) >= 0.0f) && (hi2(vcp) >= 0.0f) && (hi2(vs) <= den);
                float cpl = in1 ? hi2(dsq) : CUDART_INF_F;
                float m = fminf(fminf(hi2(cAB), hi2(cAC)), fminf(hi2(cBC), cpl));
                best1 = fminf(best1, m);
            }
        }

        best0 = fmaxf(best0, 0.0f);
        best1 = fmaxf(best1, 0.0f);
        atomicMin((int*)&g_mind2[b * NP + p0], __float_as_int(best0));
        atomicMin((int*)&g_mind2[b * NP + p0 + THREADS], __float_as_int(best1));
    }
}

// ---------------------------------------------------------------------------
// Kernel 3b: correction — exact reference cascade (round-1 verified formulation)
// for the few degenerate faces excluded from the fast path.
// ---------------------------------------------------------------------------
__global__ void correction_kernel(const float* __restrict__ points,
                                  const float* __restrict__ verts,
                                  const int*   __restrict__ faces) {
    int b = blockIdx.y;
    int n = min(g_degcnt[b], DEG_MAX);
    for (int df = blockIdx.x; df < n; df += gridDim.x) {
        int f = g_deglist[b][df];
        const int* fc = faces + ((size_t)b * NF + f) * 3;
        const float* vb = verts + (size_t)b * NV * 3;
        int ia = fc[0], ibv = fc[1], ic = fc[2];

        float ax = vb[ia * 3 + 0], ay = vb[ia * 3 + 1], az = vb[ia * 3 + 2];
        float bx = vb[ibv * 3 + 0], by = vb[ibv * 3 + 1], bz = vb[ibv * 3 + 2];
        float cx = vb[ic * 3 + 0], cy = vb[ic * 3 + 1], cz = vb[ic * 3 + 2];

        float abx = bx - ax, aby = by - ay, abz = bz - az;
        float acx = cx - ax, acy = cy - ay, acz = cz - az;

        float aa = abx * abx + aby * aby + abz * abz;
        float ad = abx * acx + aby * acy + abz * acz;
        float cc = acx * acx + acy * acy + acz * acz;
        float bb = aa + cc - 2.0f * ad;
        float den = aa * cc - ad * ad;

        float raa  = 1.0f / fmaxf(aa, EPSF);
        float rcc  = 1.0f / fmaxf(cc, EPSF);
        float rbb  = 1.0f / fmaxf(bb, EPSF);
        float rden = 1.0f / fmaxf(den, EPSF);

        for (int p = threadIdx.x; p < NP; p += blockDim.x) {
            const float* pp_ = points + ((size_t)b * NP + p) * 3;
            float apx = pp_[0] - ax, apy = pp_[1] - ay, apz = pp_[2] - az;

            float d1 = fmaf(abx, apx, fmaf(aby, apy, abz * apz));
            float d2 = fmaf(acx, apx, fmaf(acy, apy, acz * apz));
            float d3 = d1 - aa;
            float d4 = d2 - ad;
            float d5 = d1 - ad;
            float d6 = d2 - cc;

            float va = d3 * d6 - d5 * d4;
            float vbv = d5 * d2 - d1 * d6;
            float vcv = d1 * d4 - d3 * d2;

            float s = vbv * rden;
            float w = vcv * rden;

            float e46 = d4 - d3;
            float e56 = d5 - d6;
            bool c6 = (va <= 0.0f) && (e46 >= 0.0f) && (e56 >= 0.0f);
            float wbc = e46 * rbb;
            s = c6 ? (1.0f - wbc) : s;
            w = c6 ? wbc : w;

            bool c5 = (vbv <= 0.0f) && (d2 >= 0.0f) && (d6 <= 0.0f);
            s = c5 ? 0.0f : s;
            w = c5 ? (d2 * rcc) : w;

            bool c4 = (vcv <= 0.0f) && (d1 >= 0.0f) && (d3 <= 0.0f);
            s = c4 ? (d1 * raa) : s;
            w = c4 ? 0.0f : w;

            bool c3 = (d6 >= 0.0f) && (d5 <= d6);
            s = c3 ? 0.0f : s;
            w = c3 ? 1.0f : w;

            bool c2 = (d3 >= 0.0f) && (d4 <= d3);
            s = c2 ? 1.0f : s;
            w = c2 ? 0.0f : w;

            bool c1 = (d1 <= 0.0f) && (d2 <= 0.0f);
            s = c1 ? 0.0f : s;
            w = c1 ? 0.0f : w;

            float rx = apx - fmaf(s, abx, w * acx);
            float ry = apy - fmaf(s, aby, w * acy);
            float rz = apz - fmaf(s, abz, w * acz);
            float dd = fmaf(rx, rx, fmaf(ry, ry, rz * rz));
            dd = fmaxf(dd, 0.0f);
            atomicMin((int*)&g_mind2[b * NP + p], __float_as_int(dd));
        }
    }
}

// ---------------------------------------------------------------------------
// Kernel 4: finalize — sum per-point mins, height, sqrt, mean over batch.
// ---------------------------------------------------------------------------
__device__ __forceinline__ float warpSum(float v) {
#pragma unroll
    for (int o = 16; o > 0; o >>= 1) v += __shfl_down_sync(0xffffffffu, v, o);
    return v;
}
__device__ __forceinline__ float warpMax(float v) {
#pragma unroll
    for (int o = 16; o > 0; o >>= 1) v = fmaxf(v, __shfl_down_sync(0xffffffffu, v, o));
    return v;
}
__device__ __forceinline__ float warpMin(float v) {
#pragma unroll
    for (int o = 16; o > 0; o >>= 1) v = fminf(v, __shfl_down_sync(0xffffffffu, v, o));
    return v;
}

__global__ void finalize_kernel(const float* __restrict__ verts,
                                float* __restrict__ out) {
    __shared__ float sred[32];
    __shared__ float sres[4];
    int tid = threadIdx.x;
    int lane = tid & 31, wrp = tid >> 5;
    int nwarps = blockDim.x >> 5;

    for (int b = 0; b < NB; ++b) {
        float sum = 0.0f;
        for (int i = tid; i < NP; i += blockDim.x) sum += g_mind2[b * NP + i];
        sum = warpSum(sum);
        __syncthreads();
        if (lane == 0) sred[wrp] = sum;
        __syncthreads();
        if (wrp == 0) {
            float v = (lane < nwarps) ? sred[lane] : 0.0f;
            v = warpSum(v);
            if (lane == 0) sres[2] = v;
        }
        __syncthreads();
        float total = sres[2];

        float ymax = -CUDART_INF_F, ymin = CUDART_INF_F;
        for (int i = tid; i < NV; i += blockDim.x) {
            float y = verts[((size_t)b * NV + i) * 3 + 1];
            ymax = fmaxf(ymax, y);
            ymin = fminf(ymin, y);
        }
        ymax = warpMax(ymax);
        __syncthreads();
        if (lane == 0) sred[wrp] = ymax;
        __syncthreads();
        if (wrp == 0) {
            float v = (lane < nwarps) ? sred[lane] : -CUDART_INF_F;
            v = warpMax(v);
            if (lane == 0) sres[3] = v;
        }
        __syncthreads();
        float hmax = sres[3];

        ymin = warpMin(ymin);
        __syncthreads();
        if (lane == 0) sred[wrp] = ymin;
        __syncthreads();
        if (wrp == 0) {
            float v = (lane < nwarps) ? sred[lane] : CUDART_INF_F;
            v = warpMin(v);
            if (lane == 0) sres[3] = v;
        }
        __syncthreads();
        float hmin = sres[3];

        if (tid == 0) sres[b] = sqrtf(total) / (hmax - hmin);
        __syncthreads();
    }

    if (tid == 0) out[0] = 0.5f * (sres[0] + sres[1]);
}

// ---------------------------------------------------------------------------
// Entry point
// ---------------------------------------------------------------------------
extern "C" void kernel_launch(void* const* d_in, const int* in_sizes, int n_in,
                              void* d_out, int out_size) {
    const float* points = (const float*)d_in[0];  // body_verts [2,8192,3]
    const float* verts  = (const float*)d_in[1];  // mesh_verts [2,4098,3]
    const int*   faces  = (const int*)d_in[2];    // faces      [2,8192,3]
    float* out = (float*)d_out;

    init_mind2<<<(NB * NP + 255) / 256, 256>>>();
    prep_kernel<<<(NB * NF + 255) / 256, 256>>>(verts, faces);
    main_kernel<<<GRID, THREADS>>>(points);
    correction_kernel<<<dim3(8, NB), 256>>>(points, verts, faces);
    finalize_kernel<<<1, 1024>>>(verts, out);
}

// round 4
// speedup vs baseline: 1.4607x; 1.0248x over previous
#include <cuda_runtime.h>
#include <math_constants.h>

// Problem shapes (PointCloudMeshGridLoss_79070347920145)
#define NB 2
#define NP 8192
#define NV 4098
#define NF 8192
#define EPSF 1e-12f

#define THREADS   256
#define PTS_BLOCK 512                 // 2 points per thread, packed f32x2
#define PTILES    16                  // NP / PTS_BLOCK
#define TRI_CHUNK 128
#define NCHUNKS   64                  // NF / TRI_CHUNK
#define UNITS     2048                // NB * PTILES * NCHUNKS
#define GRID      296                 // 148 SMs * 2 resident blocks
#define DEG_MAX   512

typedef unsigned long long u64;

// Per-triangle record: 19 pre-duplicated f32x2 constants + pad = 10 ulonglong2 (160B)
// slots: 0 nax 1 nay 2 naz 3 abx 4 aby 5 abz 6 acx 7 acy 8 acz
//        9 aa 10 cc 11 nad 12 amd 13 bb 14 raa 15 rcc 16 rbb 17 den 18 nrden 19 pad
__device__ ulonglong2 g_tri[NB * NF * 10];
__device__ float      g_mind2[NB * NP];
__device__ int        g_degcnt[NB];
__device__ int        g_deglist[NB][DEG_MAX];

// ---------------- packed f32x2 helpers ----------------
__device__ __forceinline__ u64 pk2(float lo, float hi) {
    return ((u64)__float_as_uint(hi) << 32) | (u64)__float_as_uint(lo);
}
__device__ __forceinline__ float lo2(u64 v) { return __uint_as_float((unsigned)v); }
__device__ __forceinline__ float hi2(u64 v) { return __uint_as_float((unsigned)(v >> 32)); }
__device__ __forceinline__ u64 f2fma(u64 a, u64 b, u64 c) {
    u64 d; asm("fma.rn.f32x2 %0, %1, %2, %3;" : "=l"(d) : "l"(a), "l"(b), "l"(c)); return d;
}
__device__ __forceinline__ u64 f2mul(u64 a, u64 b) {
    u64 d; asm("mul.rn.f32x2 %0, %1, %2;" : "=l"(d) : "l"(a), "l"(b)); return d;
}
__device__ __forceinline__ u64 f2add(u64 a, u64 b) {
    u64 d; asm("add.rn.f32x2 %0, %1, %2;" : "=l"(d) : "l"(a), "l"(b)); return d;
}
// clamp each half to [0, hi.half]  (FMNMX, alu pipe)
__device__ __forceinline__ u64 f2clamp(u64 v, u64 hi) {
    float a = fminf(fmaxf(lo2(v), 0.0f), lo2(hi));
    float b = fminf(fmaxf(hi2(v), 0.0f), hi2(hi));
    return pk2(a, b);
}

// ---------------------------------------------------------------------------
// Kernel 1: per-triangle precompute. Degenerate faces excluded from fast path
// (vertex shifted 1e18 -> edge candidates ~1e36; nrden=NaN kills interior)
// and listed for exact handling in correction_kernel.
// ---------------------------------------------------------------------------
__global__ void prep_kernel(const float* __restrict__ verts,
                            const int*   __restrict__ faces) {
    int idx = blockIdx.x * blockDim.x + threadIdx.x;
    if (idx >= NB * NF) return;
    int b = idx / NF;
    int f = idx - b * NF;

    const int* fc = faces + ((size_t)b * NF + f) * 3;
    const float* vb = verts + (size_t)b * NV * 3;
    int ia = fc[0], ib = fc[1], ic = fc[2];

    float ax = vb[ia * 3 + 0], ay = vb[ia * 3 + 1], az = vb[ia * 3 + 2];
    float bx = vb[ib * 3 + 0], by = vb[ib * 3 + 1], bz = vb[ib * 3 + 2];
    float cx = vb[ic * 3 + 0], cy = vb[ic * 3 + 1], cz = vb[ic * 3 + 2];

    float abx = bx - ax, aby = by - ay, abz = bz - az;
    float acx = cx - ax, acy = cy - ay, acz = cz - az;

    float aa = abx * abx + aby * aby + abz * abz;
    float ad = abx * acx + aby * acy + abz * acz;
    float cc = acx * acx + acy * acy + acz * acz;
    float bb = aa + cc - 2.0f * ad;                 // |bc|^2
    float den = aa * cc - ad * ad;                  // |ab x ac|^2

    bool deg = (aa < 1e-9f) || (cc < 1e-9f) || (bb < 1e-9f) || (den < 1e-6f);
    if (deg) {
        int w = atomicAdd(&g_degcnt[b], 1);
        if (w < DEG_MAX) g_deglist[b][w] = f;
    }

    float raa = 1.0f / fmaxf(aa, EPSF);
    float rcc = 1.0f / fmaxf(cc, EPSF);
    float rbb = 1.0f / fmaxf(bb, EPSF);
    float nrden = deg ? __int_as_float(0x7fc00000) : (-1.0f / den);

    float shift = deg ? 1e18f : 0.0f;

    u64 s[20];
#define DUP(x) pk2((x), (x))
    s[0]  = DUP(-(ax + shift));  s[1]  = DUP(-(ay + shift));  s[2]  = DUP(-(az + shift));
    s[3]  = DUP(abx);  s[4]  = DUP(aby);  s[5]  = DUP(abz);
    s[6]  = DUP(acx);  s[7]  = DUP(acy);  s[8]  = DUP(acz);
    s[9]  = DUP(aa);   s[10] = DUP(cc);   s[11] = DUP(-ad);
    s[12] = DUP(aa - ad); s[13] = DUP(bb);
    s[14] = DUP(raa);  s[15] = DUP(rcc);  s[16] = DUP(rbb);
    s[17] = DUP(den);  s[18] = DUP(nrden); s[19] = 0ull;
#undef DUP
    ulonglong2* o = &g_tri[(size_t)idx * 10];
#pragma unroll
    for (int j = 0; j < 10; ++j) o[j] = make_ulonglong2(s[2 * j], s[2 * j + 1]);
}

// ---------------------------------------------------------------------------
// Kernel 2: init per-point min to +inf, reset degenerate counters
// ---------------------------------------------------------------------------
__global__ void init_mind2() {
    int i = blockIdx.x * blockDim.x + threadIdx.x;
    if (i < NB * NP) g_mind2[i] = CUDART_INF_F;
    if (i < NB) g_degcnt[i] = 0;
}

// ---------------------------------------------------------------------------
// Kernel 3: main scan — packed f32x2, pp-relative candidates, sign-trick gate
// ---------------------------------------------------------------------------
__global__ __launch_bounds__(THREADS, 2)
void main_kernel(const float* __restrict__ points) {
    __shared__ ulonglong2 s_tri[TRI_CHUNK * 10];   // 20 KB

    const u64 NEG2    = 0xC0000000C0000000ULL;     // (-2, -2)
    const u64 NEGONE2 = 0xBF800000BF800000ULL;     // (-1, -1)

    for (int u = blockIdx.x; u < UNITS; u += GRID) {
        int b     = u >> 10;
        int rem   = u & 1023;
        int ptile = rem >> 6;
        int chunk = rem & 63;

        __syncthreads();
        {
            const ulonglong2* src = &g_tri[((size_t)b * NF + (size_t)chunk * TRI_CHUNK) * 10];
            for (int i = threadIdx.x; i < TRI_CHUNK * 10; i += THREADS)
                s_tri[i] = src[i];
        }

        int p0 = ptile * PTS_BLOCK + threadIdx.x;
        const float* P = points + ((size_t)b * NP + p0) * 3;
        u64 px = pk2(P[0], P[THREADS * 3 + 0]);
        u64 py = pk2(P[1], P[THREADS * 3 + 1]);
        u64 pz = pk2(P[2], P[THREADS * 3 + 2]);
        float best0 = CUDART_INF_F, best1 = CUDART_INF_F;

        __syncthreads();

        for (int t = 0; t < TRI_CHUNK; ++t) {
            const ulonglong2* ct = &s_tri[t * 10];
            ulonglong2 c0 = ct[0], c1 = ct[1], c2 = ct[2], c3 = ct[3], c4 = ct[4];
            ulonglong2 c5 = ct[5], c6 = ct[6], c7 = ct[7], c8 = ct[8];
            u64 nrden = ct[9].x;
            u64 nax = c0.x, nay = c0.y, naz = c1.x, abx = c1.y, aby = c2.x, abz = c2.y;
            u64 acx = c3.x, acy = c3.y, acz = c4.x, aa = c4.y, cc = c5.x, nad = c5.y;
            u64 amd = c6.x, bb = c6.y, raa = c7.x, rcc = c7.y, rbb = c8.x, den = c8.y;

            u64 apx = f2add(px, nax);
            u64 apy = f2add(py, nay);
            u64 apz = f2add(pz, naz);

            u64 d1 = f2fma(abz, apz, f2fma(aby, apy, f2mul(abx, apx)));
            u64 d2 = f2fma(acz, apz, f2fma(acy, apy, f2mul(acx, apx)));
            u64 pp = f2fma(apz, apz, f2fma(apy, apy, f2mul(apx, apx)));

            // edge AB: q = raa*u*(u - 2*d1), u = clamp(d1, 0, aa)   (q <= 0)
            u64 uA = f2clamp(d1, aa);
            u64 sA = f2fma(d1, NEG2, uA);
            u64 qA = f2mul(f2mul(uA, raa), sA);

            // edge AC
            u64 uC = f2clamp(d2, cc);
            u64 sC = f2fma(d2, NEG2, uC);
            u64 qC = f2mul(f2mul(uC, rcc), sC);

            // edge BC (relative to pp): qBC = rbb*u*(u-2*e46) + (aa - 2*d1)
            u64 e46 = f2fma(d1, NEGONE2, f2add(d2, amd));
            u64 uB  = f2clamp(e46, bb);
            u64 sB  = f2fma(e46, NEG2, uB);
            u64 qB  = f2mul(f2mul(uB, rbb), sB);
            u64 aa2 = f2fma(d1, NEG2, aa);
            u64 qBC = f2add(qB, aa2);

            // inside test values
            u64 vbp = f2fma(nad, d2, f2mul(cc, d1));
            u64 vcp = f2fma(nad, d1, f2mul(aa, d2));
            u64 dvs = f2fma(f2add(vbp, vcp), NEGONE2, den);   // den - (vb+vc)

            // interior: qin = -(vb*d1 + vc*d2)/den  (pp-relative, <= 0)
            u64 qin = f2mul(f2fma(vcp, d2, f2mul(vbp, d1)), nrden);

            // half 0
            {
                unsigned badb = (unsigned)vbp | (unsigned)vcp | (unsigned)dvs;
                unsigned msk  = (unsigned)(((int)badb) >> 31) & 0x7fc00000u;
                float qg = __uint_as_float((unsigned)qin | msk);   // NaN if outside
                float m  = fminf(fminf(lo2(qA), lo2(qC)), fminf(lo2(qBC), qg));
                best0 = fminf(best0, lo2(pp) + m);
            }
            // half 1
            {
                unsigned badb = (unsigned)(vbp >> 32) | (unsigned)(vcp >> 32) | (unsigned)(dvs >> 32);
                unsigned msk  = (unsigned)(((int)badb) >> 31) & 0x7fc00000u;
                float qg = __uint_as_float((unsigned)(qin >> 32) | msk);
                float m  = fminf(fminf(hi2(qA), hi2(qC)), fminf(hi2(qBC), qg));
                best1 = fminf(best1, hi2(pp) + m);
            }
        }

        best0 = fmaxf(best0, 0.0f);
        best1 = fmaxf(best1, 0.0f);
        atomicMin((int*)&g_mind2[b * NP + p0], __float_as_int(best0));
        atomicMin((int*)&g_mind2[b * NP + p0 + THREADS], __float_as_int(best1));
    }
}

// ---------------------------------------------------------------------------
// Kernel 3b: correction — exact reference cascade for degenerate faces.
// Parallel over POINTS (grid 32 x NB); loops the few flagged faces.
// ---------------------------------------------------------------------------
__global__ void correction_kernel(const float* __restrict__ points,
                                  const float* __restrict__ verts,
                                  const int*   __restrict__ faces) {
    int b = blockIdx.y;
    int n = min(g_degcnt[b], DEG_MAX);
    if (n == 0) return;

    int p = blockIdx.x * blockDim.x + threadIdx.x;   // 32*256 = 8192 = NP
    const float* pp_ = points + ((size_t)b * NP + p) * 3;
    float ppx = pp_[0], ppy = pp_[1], ppz = pp_[2];
    float best = CUDART_INF_F;

    const float* vb = verts + (size_t)b * NV * 3;
    for (int df = 0; df < n; ++df) {
        int f = g_deglist[b][df];
        const int* fc = faces + ((size_t)b * NF + f) * 3;
        int ia = fc[0], ibv = fc[1], ic = fc[2];

        float ax = vb[ia * 3 + 0], ay = vb[ia * 3 + 1], az = vb[ia * 3 + 2];
        float bx = vb[ibv * 3 + 0], by = vb[ibv * 3 + 1], bz = vb[ibv * 3 + 2];
        float cx = vb[ic * 3 + 0], cy = vb[ic * 3 + 1], cz = vb[ic * 3 + 2];

        float abx = bx - ax, aby = by - ay, abz = bz - az;
        float acx = cx - ax, acy = cy - ay, acz = cz - az;

        float aa = abx * abx + aby * aby + abz * abz;
        float ad = abx * acx + aby * acy + abz * acz;
        float cc = acx * acx + acy * acy + acz * acz;
        float bbq = aa + cc - 2.0f * ad;
        float den = aa * cc - ad * ad;

        float raa  = 1.0f / fmaxf(aa, EPSF);
        float rcc  = 1.0f / fmaxf(cc, EPSF);
        float rbb  = 1.0f / fmaxf(bbq, EPSF);
        float rden = 1.0f / fmaxf(den, EPSF);

        float apx = ppx - ax, apy = ppy - ay, apz = ppz - az;

        float d1 = fmaf(abx, apx, fmaf(aby, apy, abz * apz));
        float d2 = fmaf(acx, apx, fmaf(acy, apy, acz * apz));
        float d3 = d1 - aa;
        float d4 = d2 - ad;
        float d5 = d1 - ad;
        float d6 = d2 - cc;

        float va = d3 * d6 - d5 * d4;
        float vbv = d5 * d2 - d1 * d6;
        float vcv = d1 * d4 - d3 * d2;

        float s = vbv * rden;
        float w = vcv * rden;

        float e46 = d4 - d3;
        float e56 = d5 - d6;
        bool c6 = (va <= 0.0f) && (e46 >= 0.0f) && (e56 >= 0.0f);
        float wbc = e46 * rbb;
        s = c6 ? (1.0f - wbc) : s;
        w = c6 ? wbc : w;

        bool c5 = (vbv <= 0.0f) && (d2 >= 0.0f) && (d6 <= 0.0f);
        s = c5 ? 0.0f : s;
        w = c5 ? (d2 * rcc) : w;

        bool c4 = (vcv <= 0.0f) && (d1 >= 0.0f) && (d3 <= 0.0f);
        s = c4 ? (d1 * raa) : s;
        w = c4 ? 0.0f : w;

        bool c3 = (d6 >= 0.0f) && (d5 <= d6);
        s = c3 ? 0.0f : s;
        w = c3 ? 1.0f : w;

        bool c2 = (d3 >= 0.0f) && (d4 <= d3);
        s = c2 ? 1.0f : s;
        w = c2 ? 0.0f : w;

        bool c1 = (d1 <= 0.0f) && (d2 <= 0.0f);
        s = c1 ? 0.0f : s;
        w = c1 ? 0.0f : w;

        float rx = apx - fmaf(s, abx, w * acx);
        float ry = apy - fmaf(s, aby, w * acy);
        float rz = apz - fmaf(s, abz, w * acz);
        float dd = fmaf(rx, rx, fmaf(ry, ry, rz * rz));
        best = fminf(best, dd);
    }
    best = fmaxf(best, 0.0f);
    atomicMin((int*)&g_mind2[b * NP + p], __float_as_int(best));
}

// ---------------------------------------------------------------------------
// Kernel 4: finalize — both batches concurrently in one block (two 512-thread halves)
// ---------------------------------------------------------------------------
__device__ __forceinline__ float warpSum(float v) {
#pragma unroll
    for (int o = 16; o > 0; o >>= 1) v += __shfl_down_sync(0xffffffffu, v, o);
    return v;
}
__device__ __forceinline__ float warpMax(float v) {
#pragma unroll
    for (int o = 16; o > 0; o >>= 1) v = fmaxf(v, __shfl_down_sync(0xffffffffu, v, o));
    return v;
}
__device__ __forceinline__ float warpMin(float v) {
#pragma unroll
    for (int o = 16; o > 0; o >>= 1) v = fminf(v, __shfl_down_sync(0xffffffffu, v, o));
    return v;
}

__global__ void finalize_kernel(const float* __restrict__ verts,
                                float* __restrict__ out) {
    __shared__ float s_sum[32], s_max[32], s_min[32];
    __shared__ float s_loss[2];
    int tid  = threadIdx.x;        // 0..1023
    int b    = tid >> 9;           // batch handled by this half
    int lt   = tid & 511;
    int wid  = tid >> 5;           // 0..31
    int lane = tid & 31;

    float sum = 0.0f;
    for (int i = lt; i < NP; i += 512) sum += g_mind2[b * NP + i];

    float ymax = -CUDART_INF_F, ymin = CUDART_INF_F;
    for (int i = lt; i < NV; i += 512) {
        float y = verts[((size_t)b * NV + i) * 3 + 1];
        ymax = fmaxf(ymax, y);
        ymin = fminf(ymin, y);
    }

    sum  = warpSum(sum);
    ymax = warpMax(ymax);
    ymin = warpMin(ymin);
    if (lane == 0) { s_sum[wid] = sum; s_max[wid] = ymax; s_min[wid] = ymin; }
    __syncthreads();

    if (lt < 32) {  // first warp of each half reduces its 16 warp-partials
        int base = b * 16;
        float v  = (lane < 16) ? s_sum[base + lane] : 0.0f;
        float mx = (lane < 16) ? s_max[base + lane] : -CUDART_INF_F;
        float mn = (lane < 16) ? s_min[base + lane] : CUDART_INF_F;
        v  = warpSum(v);
        mx = warpMax(mx);
        mn = warpMin(mn);
        if (lane == 0) s_loss[b] = sqrtf(v) / (mx - mn);
    }
    __syncthreads();

    if (tid == 0) out[0] = 0.5f * (s_loss[0] + s_loss[1]);
}

// ---------------------------------------------------------------------------
// Entry point
// ---------------------------------------------------------------------------
extern "C" void kernel_launch(void* const* d_in, const int* in_sizes, int n_in,
                              void* d_out, int out_size) {
    const float* points = (const float*)d_in[0];  // body_verts [2,8192,3]
    const float* verts  = (const float*)d_in[1];  // mesh_verts [2,4098,3]
    const int*   faces  = (const int*)d_in[2];    // faces      [2,8192,3]
    float* out = (float*)d_out;

    init_mind2<<<(NB * NP + 255) / 256, 256>>>();
    prep_kernel<<<(NB * NF + 255) / 256, 256>>>(verts, faces);
    main_kernel<<<GRID, THREADS>>>(points);
    correction_kernel<<<dim3(NP / 256, NB), 256>>>(points, verts, faces);
    finalize_kernel<<<1, 1024>>>(verts, out);
}